// round 8
// baseline (speedup 1.0000x reference)
#include <cuda_runtime.h>
#include <math.h>

// Problem constants (fixed by setup_inputs: B=128, S=300, G=100)
#define S_DIM 300
#define SPAD  320
#define G_DIM 100
#define B_MAX 128
#define NTHREADS 320
#define NWARPS (NTHREADS / 32)
#define KSLOTS 10
#define BIGC  1.0e30f
#define FREECAP 256

#define CLASS_W 1.0
#define COORD_W 5.0
#define WIDTH_W 2.0
#define P0_W    2.0

static __device__ double   g_part[B_MAX * 5];
static __device__ unsigned g_done = 0;

// All costs carry a +1.0f offset so every entry is >= 0, and v only ever
// decreases (v <= 0), so C - v >= 0 and reduced Dijkstra distances >= 0.
// For non-negative IEEE floats raw bits are order-isomorphic to values, so
// argmin keys are plain __float_as_uint(x).
// ARR cache invariant: v decreases => reduced costs only INCREASE, and only
// at tightened columns. A row's phase-3 (min1,c1,min2,c2) stays exact while
// both c1 and c2 are untouched (sh_dirty check).

extern __shared__ float s_C[];    // [G_DIM * SPAD] f32 cost matrix (128 KB)

// pairwise merge preferring LEFT on ties (left = smaller column)
__device__ __forceinline__ void kmerge(unsigned& kL, int& cL, unsigned kR, int cR) {
    if (kR < kL) { kL = kR; cL = cR; }
}

__global__ __launch_bounds__(NTHREADS, 1)
void detr_batch_kernel(const float* __restrict__ strokes,
                       const float* __restrict__ logits,
                       const float* __restrict__ tparams,
                       const int*   __restrict__ tlabels,
                       float* __restrict__ out)
{
    const int b    = blockIdx.x;
    const int tid  = threadIdx.x;
    const int wid  = tid >> 5;
    const int lane = tid & 31;

    __shared__ float  sh_strokes[S_DIM * 10];
    __shared__ float  sh_tpv[G_DIM * 12];
    __shared__ float  sh_nll[S_DIM * 3];
    __shared__ float  sh_u[G_DIM];
    __shared__ float  sh_rm1[G_DIM];
    __shared__ float  sh_rm2[G_DIM];
    __shared__ float  sh_minStep[G_DIM + 4];
    __shared__ int    sh_row4col[SPAD];
    __shared__ int    sh_col4row[G_DIM];
    __shared__ int    sh_path[SPAD];
    __shared__ int    sh_SR[G_DIM + 4];
    __shared__ int    sh_valid[G_DIM];
    __shared__ int    sh_cls[G_DIM];
    __shared__ int    sh_cand[G_DIM];
    __shared__ int    sh_rc2[G_DIM];
    __shared__ int    sh_free[FREECAP];
    __shared__ int    sh_dij[FREECAP];
    __shared__ int    sh_owner[SPAD];
    __shared__ unsigned char sh_dirty[SPAD];
    __shared__ int    sh_nv, sh_nf, sh_last;
    __shared__ double sh_acc[NWARPS * 3];
    __shared__ double sh_ceb[NWARPS];

    // ---- Phase 0 (warp 0): valid-target compaction; all: staging ----
    if (tid < 32) {
        int base = 0;
        #pragma unroll
        for (int c = 0; c < 4; c++) {
            int g = c * 32 + tid;
            int l = (g < G_DIM) ? tlabels[(size_t)b * G_DIM + g] : 0;
            unsigned bal = __ballot_sync(0xffffffffu, l > 0);
            if (l > 0) {
                int rank = base + __popc(bal & ((1u << tid) - 1u));
                sh_valid[rank] = g;
                sh_cls[rank]   = l;
            }
            base += __popc(bal);
        }
        if (tid == 0) sh_nv = base;
    }

    const int j = tid;
    const bool active = (j < S_DIM);

    float sp[10];
    float pc1 = 1.0f, pc2 = 1.0f;     // 1 - prob_c  (>= 0, offset folded in)
    if (active) {
        const float* g = strokes + ((size_t)b * S_DIM + j) * 10;
        #pragma unroll
        for (int d = 0; d < 10; d++) { sp[d] = g[d]; sh_strokes[j * 10 + d] = sp[d]; }

        const float* lg = logits + ((size_t)b * S_DIM + j) * 3;
        float l0 = lg[0], l1 = lg[1], l2 = lg[2];
        float mx = fmaxf(l0, fmaxf(l1, l2));
        float e0 = expf(l0 - mx), e1 = expf(l1 - mx), e2 = expf(l2 - mx);
        float s  = e0 + e1 + e2;
        pc1 = 1.0f - (e1 / s);
        pc2 = 1.0f - (e2 / s);
        float lse = mx + logf(s);
        sh_nll[j * 3 + 0] = lse - l0;
        sh_nll[j * 3 + 1] = lse - l1;
        sh_nll[j * 3 + 2] = lse - l2;
    }
    for (int p = tid; p < SPAD; p += NTHREADS) {
        sh_row4col[p] = -1;
        sh_owner[p] = 0x7fffffff;
        sh_dirty[p] = 0;
    }
    for (int p = tid; p < G_DIM; p += NTHREADS) sh_col4row[p] = -1;
    __syncthreads();

    const int nv = sh_nv;

    // ---- Phase 1: gather valid target params (stride 12) ----
    for (int k = tid; k < nv * 10; k += NTHREADS) {
        int i = k / 10, d = k - i * 10;
        sh_tpv[i * 12 + d] = tparams[((size_t)b * G_DIM + sh_valid[i]) * 10 + d];
    }
    __syncthreads();

    // ---- Phase 2: cost build, column-per-thread (all entries >= 0) ----
    for (int i = 0; i < nv; i++) {
        float4 t0 = *(const float4*)&sh_tpv[i * 12 + 0];
        float4 t1 = *(const float4*)&sh_tpv[i * 12 + 4];
        float  t8 = sh_tpv[i * 12 + 8];
        float  t9 = sh_tpv[i * 12 + 9];
        float acc;
        if (active) {
            acc = (sh_cls[i] == 1) ? pc1 : pc2;
            acc += 7.0f * fabsf(sp[0] - t0.x);
            acc += 7.0f * fabsf(sp[1] - t0.y);
            acc += 5.0f * fabsf(sp[2] - t0.z);
            acc += 5.0f * fabsf(sp[3] - t0.w);
            acc += 5.0f * fabsf(sp[4] - t1.x);
            acc += 5.0f * fabsf(sp[5] - t1.y);
            acc += 5.0f * fabsf(sp[6] - t1.z);
            acc += 5.0f * fabsf(sp[7] - t1.w);
            acc += 2.0f * fabsf(sp[8] - t8);
            acc += 2.0f * fabsf(sp[9] - t9);
        } else {
            acc = BIGC;
        }
        s_C[i * SPAD + j] = acc;
    }
    __syncthreads();

    // ---- Phase 3: per-row (min1,c1,min2,c2) -> duals + greedy + ARR cache ----
    for (int row = wid; row < nv; row += NWARPS) {
        const float* Crow = s_C + row * SPAD;
        unsigned m1 = 0xFFFFFFFFu, m2 = 0xFFFFFFFFu;
        int c1 = 0x7fffffff, c2 = 0x7fffffff;
        #pragma unroll
        for (int k = 0; k < KSLOTS; k++) {
            int col = lane + 32 * k;
            unsigned x = __float_as_uint(Crow[col]);
            if (x < m1) { m2 = m1; c2 = c1; m1 = x; c1 = col; }
            else if (x < m2) { m2 = x; c2 = col; }
        }
        unsigned g1 = __reduce_min_sync(0xffffffffu, m1);
        unsigned s1 = (m1 == g1) ? (unsigned)c1 : 0xFFFFFFFFu;
        unsigned j1 = __reduce_min_sync(0xffffffffu, s1);
        int winlane = (int)(j1 & 31u);
        unsigned candv = (lane == winlane) ? m2 : m1;
        int      candc = (lane == winlane) ? c2 : c1;
        unsigned g2 = __reduce_min_sync(0xffffffffu, candv);
        unsigned s2 = (candv == g2) ? (unsigned)candc : 0xFFFFFFFFu;
        unsigned j2 = __reduce_min_sync(0xffffffffu, s2);
        if (lane == 0) {
            sh_u[row]   = __uint_as_float(g1);
            sh_cand[row] = (int)j1;
            sh_rm1[row] = __uint_as_float(g1);
            sh_rm2[row] = __uint_as_float(g2);
            sh_rc2[row] = (int)j2;
        }
    }
    __syncthreads();

    // ---- Phase 4a: parallel greedy conflict resolution (winner = min row) ----
    for (int i = tid; i < nv; i += NTHREADS)
        atomicMin_block(&sh_owner[sh_cand[i]], i);
    __syncthreads();

    if (tid < 32) {
        int base = 0;
        #pragma unroll
        for (int c = 0; c < 4; c++) {
            int i = c * 32 + tid;
            bool isfree = false;
            if (i < nv) {
                int cj = sh_cand[i];
                if (sh_owner[cj] == i) { sh_col4row[i] = cj; sh_row4col[cj] = i; }
                else isfree = true;
            }
            unsigned bal = __ballot_sync(0xffffffffu, isfree);
            if (isfree) {
                int rank = base + __popc(bal & ((1u << tid) - 1u));
                sh_free[rank] = i;
            }
            base += __popc(bal);
        }
        if (tid == 0) sh_nf = base;
    }
    __syncthreads();

    // ---- Phase 4b: warp 0 — cached ARR + Dijkstra; warps 1-9 — CE base ----
    if (tid < 32) {
        float v_[KSLOTS];                  // column duals, v <= 0 always
        #pragma unroll
        for (int k = 0; k < KSLOTS; k++) v_[k] = 0.0f;

        // ---- ARR: assign each free row tightly at its min1 column ----
        int h = 0, t = sh_nf, nd = 0;
        int ops = 0;
        const int cap = 2 * nv + 8;
        while (h < t) {
            if (ops >= cap || t >= FREECAP - 1) {
                for (int q = h + (int)lane; q < t; q += 32)
                    sh_dij[nd + (q - h)] = sh_free[q];
                nd += t - h;
                break;
            }
            ops++;
            const int i = sh_free[h++];

            unsigned g1, g2; int j1;
            {
                int cc1 = sh_cand[i], cc2 = sh_rc2[i];
                if ((sh_dirty[cc1] | sh_dirty[cc2]) == 0) {
                    // cache exact: reduced costs only grew, and not at cc1/cc2
                    g1 = __float_as_uint(sh_rm1[i]);
                    g2 = __float_as_uint(sh_rm2[i]);
                    j1 = cc1;
                } else {
                    const float* Crow = s_C + i * SPAD;
                    unsigned m1 = 0xFFFFFFFFu, m2 = 0xFFFFFFFFu; int c1 = 0;
                    #pragma unroll
                    for (int k = 0; k < KSLOTS; k++) {
                        unsigned x = __float_as_uint(Crow[lane + 32 * k] - v_[k]);
                        if (x < m1) { m2 = m1; m1 = x; c1 = lane + 32 * k; }
                        else if (x < m2) m2 = x;
                    }
                    g1 = __reduce_min_sync(0xffffffffu, m1);
                    unsigned bal = __ballot_sync(0xffffffffu, m1 == g1);
                    int winlane = __ffs(bal) - 1;
                    unsigned cand = (lane == winlane) ? m2 : m1;
                    g2 = __reduce_min_sync(0xffffffffu, cand);
                    j1 = __shfl_sync(0xffffffffu, c1, winlane);
                }
            }

            int owner = sh_row4col[j1];
            if (g1 == g2 && owner >= 0) {   // exact tie on occupied col: defer
                if (lane == 0) sh_dij[nd] = i;
                nd++;
                continue;
            }
            float min1 = __uint_as_float(g1);
            float min2 = __uint_as_float(g2);
            sh_u[i] = min2;                              // lockstep same-value write
            if (g1 != g2) {
                if (lane == (j1 & 31))
                    v_[j1 >> 5] -= (min2 - min1);        // tighten new arc
                sh_dirty[j1] = 1;                        // invalidate caches
            }
            sh_row4col[j1] = i;
            sh_col4row[i] = j1;
            if (owner >= 0) {
                sh_col4row[owner] = -1;
                sh_free[t++] = owner;                    // displaced row re-queued
            }
            __syncwarp();
        }
        __syncwarp();

        // ---- Dijkstra augmentation for the leftover rows ----
        for (int f = 0; f < nd; f++) {
            const int cur = sh_dij[f];
            float shortest[KSLOTS];
            unsigned scmask = 0;
            #pragma unroll
            for (int k = 0; k < KSLOTS; k++) shortest[k] = 3.0e38f;

            int   i      = cur;
            float u_i    = sh_u[cur];
            const float* Crow = s_C + i * SPAD;
            float minVal = 0.0f;
            int   tt     = 0;
            int   sink   = -1;

            while (true) {
                float base = minVal - u_i;

                unsigned k_[KSLOTS]; int c_[KSLOTS];
                #pragma unroll
                for (int k = 0; k < KSLOTS; k++) {
                    int col = lane + 32 * k;
                    c_[k] = col;
                    if (!((scmask >> k) & 1u)) {           // SC guard: load-bearing
                        float d = fmaxf(base + Crow[col] - v_[k], 0.0f);
                        if (d < shortest[k]) { shortest[k] = d; sh_path[col] = i; }
                        k_[k] = __float_as_uint(shortest[k]);
                    } else {
                        k_[k] = 0xFFFFFFFFu;
                    }
                }
                kmerge(k_[0], c_[0], k_[1], c_[1]);
                kmerge(k_[2], c_[2], k_[3], c_[3]);
                kmerge(k_[4], c_[4], k_[5], c_[5]);
                kmerge(k_[6], c_[6], k_[7], c_[7]);
                kmerge(k_[8], c_[8], k_[9], c_[9]);
                kmerge(k_[0], c_[0], k_[2], c_[2]);
                kmerge(k_[4], c_[4], k_[6], c_[6]);
                kmerge(k_[0], c_[0], k_[4], c_[4]);
                kmerge(k_[0], c_[0], k_[8], c_[8]);

                unsigned gm = __reduce_min_sync(0xffffffffu, k_[0]);
                unsigned cc = (k_[0] == gm) ? (unsigned)c_[0] : 0xFFFFFFFFu;
                unsigned js = __reduce_min_sync(0xffffffffu, cc);

                minVal = __uint_as_float(gm);
                if (lane == 0) { sh_SR[tt] = i; sh_minStep[tt] = minVal; }
                if (lane == (int)(js & 31u)) scmask |= 1u << (js >> 5);
                tt++;

                int r = sh_row4col[js];
                if (r < 0) { sink = (int)js; break; }
                i = r;
                u_i = sh_u[i];
                Crow = s_C + i * SPAD;
            }
            __syncwarp();

            if (lane == 0) sh_u[cur] += minVal;
            for (int s2 = 1 + lane; s2 < tt; s2 += 32)
                sh_u[sh_SR[s2]] += minVal - sh_minStep[s2 - 1];
            #pragma unroll
            for (int k = 0; k < KSLOTS; k++)
                if ((scmask >> k) & 1u) v_[k] -= minVal - shortest[k];
            __syncwarp();

            {
                int jj = sink;
                while (true) {
                    int i2 = sh_path[jj];
                    sh_row4col[jj] = i2;
                    int nxt = sh_col4row[i2];
                    sh_col4row[i2] = jj;
                    if (i2 == cur) break;
                    jj = nxt;
                }
            }
            __syncwarp();
        }
    } else {
        // ---- warps 1..9: CE base sum (all slots as class 0), overlapped ----
        double part = 0.0;
        for (int s = tid - 32; s < S_DIM; s += NTHREADS - 32)
            part += (double)(0.1f * sh_nll[s * 3 + 0]);
        #pragma unroll
        for (int off = 16; off; off >>= 1)
            part += __shfl_down_sync(0xffffffffu, part, off);
        if (lane == 0) sh_ceb[wid] = part;
    }
    __syncthreads();

    // ---- Phase 5: losses. CE = base + per-match correction; den closed-form ----
    double ce_corr = 0.0, csum = 0.0, wsum = 0.0;

    for (int k = tid; k < nv; k += NTHREADS) {
        int s = sh_col4row[k];
        int c = sh_cls[k];
        ce_corr += (double)sh_nll[s * 3 + c] - (double)(0.1f * sh_nll[s * 3 + 0]);
        const float* spv = sh_strokes + s * 10;
        const float* tp  = sh_tpv + k * 12;
        #pragma unroll
        for (int d8 = 0; d8 < 8; d8++) {
            float ad = fabsf(spv[d8] - tp[d8]);
            float sl = (ad < 0.1f) ? (0.5f * ad * ad / 0.1f) : (ad - 0.05f);
            csum += (double)ad + (double)sl;
        }
        wsum += (double)fabsf(spv[8] - tp[8]) + (double)fabsf(spv[9] - tp[9]);
    }

    #pragma unroll
    for (int off = 16; off; off >>= 1) {
        ce_corr += __shfl_down_sync(0xffffffffu, ce_corr, off);
        csum    += __shfl_down_sync(0xffffffffu, csum,    off);
        wsum    += __shfl_down_sync(0xffffffffu, wsum,    off);
    }
    if (lane == 0) {
        sh_acc[wid * 3 + 0] = ce_corr;
        sh_acc[wid * 3 + 1] = csum;
        sh_acc[wid * 3 + 2] = wsum;
    }
    __syncthreads();

    // ---- Phase 6: per-batch partials + fused finalize (last block) ----
    if (tid == 0) {
        double a0 = 0.0, a2 = 0.0, a3 = 0.0;
        #pragma unroll
        for (int w = 0; w < NWARPS; w++) {
            a0 += sh_acc[w * 3 + 0];
            a2 += sh_acc[w * 3 + 1];
            a3 += sh_acc[w * 3 + 2];
        }
        #pragma unroll
        for (int w = 1; w < NWARPS; w++) a0 += sh_ceb[w];
        double den = (double)(S_DIM - nv) * (double)0.1f + (double)nv;
        g_part[b * 5 + 0] = a0;
        g_part[b * 5 + 1] = den;
        g_part[b * 5 + 2] = a2;
        g_part[b * 5 + 3] = a3;
        g_part[b * 5 + 4] = (double)nv;
        __threadfence();
        unsigned old = atomicInc(&g_done, gridDim.x - 1);
        sh_last = (old == gridDim.x - 1) ? 1 : 0;
    }
    __syncthreads();

    if (sh_last && tid < 32) {
        __threadfence();
        const volatile double* gp = g_part;
        double a0 = 0.0, a1 = 0.0, a2 = 0.0, a3 = 0.0, a4 = 0.0;
        for (int bb = lane; bb < (int)gridDim.x; bb += 32) {
            a0 += gp[bb * 5 + 0];
            a1 += gp[bb * 5 + 1];
            a2 += gp[bb * 5 + 2];
            a3 += gp[bb * 5 + 3];
            a4 += gp[bb * 5 + 4];
        }
        #pragma unroll
        for (int off = 16; off; off >>= 1) {
            a0 += __shfl_down_sync(0xffffffffu, a0, off);
            a1 += __shfl_down_sync(0xffffffffu, a1, off);
            a2 += __shfl_down_sync(0xffffffffu, a2, off);
            a3 += __shfl_down_sync(0xffffffffu, a3, off);
            a4 += __shfl_down_sync(0xffffffffu, a4, off);
        }
        if (lane == 0) {
            double denom = a4 > 1.0 ? a4 : 1.0;
            double loss = CLASS_W * (a0 / a1)
                        + COORD_W * (a2 / denom)
                        + WIDTH_W * (a3 / denom);
            out[0] = (float)loss;
        }
    }
}

extern "C" void kernel_launch(void* const* d_in, const int* in_sizes, int n_in,
                              void* d_out, int out_size)
{
    const float* strokes = (const float*)d_in[0];
    const float* logits  = (const float*)d_in[1];
    const float* tparams = (const float*)d_in[2];
    const int*   tlabels = (const int*)d_in[3];

    int B = in_sizes[3] / G_DIM;
    if (B > B_MAX) B = B_MAX;

    const int dyn_smem = G_DIM * SPAD * (int)sizeof(float);   // 128000 B
    cudaFuncSetAttribute(detr_batch_kernel,
                         cudaFuncAttributeMaxDynamicSharedMemorySize, dyn_smem);

    detr_batch_kernel<<<B, NTHREADS, dyn_smem>>>(strokes, logits, tparams, tlabels,
                                                 (float*)d_out);
}

// round 9
// speedup vs baseline: 1.1324x; 1.1324x over previous
#include <cuda_runtime.h>
#include <math.h>

// Problem constants (fixed by setup_inputs: B=128, S=300, G=100)
#define S_DIM 300
#define SPAD  320
#define G_DIM 100
#define B_MAX 128
#define NTHREADS 320
#define NWARPS (NTHREADS / 32)
#define KSLOTS 10
#define BIGC  1.0e30f
#define FREECAP 256

#define CLASS_W 1.0
#define COORD_W 5.0
#define WIDTH_W 2.0
#define P0_W    2.0

static __device__ double   g_part[B_MAX * 5];
static __device__ unsigned g_done = 0;

// All costs carry a +1.0f offset so every entry is >= 0, and v only ever
// decreases (v <= 0), so C - v >= 0 and reduced Dijkstra distances >= 0.
// For non-negative IEEE floats raw bits are order-isomorphic to values, so
// argmin keys are plain __float_as_uint(x).

extern __shared__ float s_C[];    // [G_DIM * SPAD] f32 cost matrix (128 KB)

// pairwise merge preferring LEFT on ties (left = smaller column)
__device__ __forceinline__ void kmerge(unsigned& kL, int& cL, unsigned kR, int cR) {
    if (kR < kL) { kL = kR; cL = cR; }
}

__global__ __launch_bounds__(NTHREADS, 1)
void detr_batch_kernel(const float* __restrict__ strokes,
                       const float* __restrict__ logits,
                       const float* __restrict__ tparams,
                       const int*   __restrict__ tlabels,
                       float* __restrict__ out)
{
    const int b    = blockIdx.x;
    const int tid  = threadIdx.x;
    const int wid  = tid >> 5;
    const int lane = tid & 31;

    __shared__ float  sh_strokes[S_DIM * 10];
    __shared__ float  sh_tpv[G_DIM * 12];
    __shared__ float  sh_nll[S_DIM * 3];
    __shared__ float  sh_u[G_DIM];
    __shared__ float  sh_minStep[G_DIM + 4];
    __shared__ int    sh_row4col[SPAD];
    __shared__ int    sh_col4row[G_DIM];
    __shared__ int    sh_path[SPAD];
    __shared__ int    sh_SR[G_DIM + 4];
    __shared__ int    sh_valid[G_DIM];
    __shared__ int    sh_cls[G_DIM];
    __shared__ int    sh_cand[G_DIM];
    __shared__ int    sh_free[FREECAP];
    __shared__ int    sh_dij[FREECAP];
    __shared__ int    sh_owner[SPAD];
    __shared__ int    sh_nv, sh_nf, sh_last;
    __shared__ double sh_acc[NWARPS * 3];
    __shared__ double sh_ceb[NWARPS];

    // ---- Phase 0 (warp 0): valid-target compaction; all: staging ----
    if (tid < 32) {
        int base = 0;
        #pragma unroll
        for (int c = 0; c < 4; c++) {
            int g = c * 32 + tid;
            int l = (g < G_DIM) ? tlabels[(size_t)b * G_DIM + g] : 0;
            unsigned bal = __ballot_sync(0xffffffffu, l > 0);
            if (l > 0) {
                int rank = base + __popc(bal & ((1u << tid) - 1u));
                sh_valid[rank] = g;
                sh_cls[rank]   = l;
            }
            base += __popc(bal);
        }
        if (tid == 0) sh_nv = base;
    }

    const int j = tid;
    const bool active = (j < S_DIM);

    float sp[10];
    float pc1 = 1.0f, pc2 = 1.0f;     // 1 - prob_c  (>= 0, offset folded in)
    if (active) {
        const float* g = strokes + ((size_t)b * S_DIM + j) * 10;
        #pragma unroll
        for (int d = 0; d < 10; d++) { sp[d] = g[d]; sh_strokes[j * 10 + d] = sp[d]; }

        const float* lg = logits + ((size_t)b * S_DIM + j) * 3;
        float l0 = lg[0], l1 = lg[1], l2 = lg[2];
        float mx = fmaxf(l0, fmaxf(l1, l2));
        float e0 = expf(l0 - mx), e1 = expf(l1 - mx), e2 = expf(l2 - mx);
        float s  = e0 + e1 + e2;
        pc1 = 1.0f - (e1 / s);
        pc2 = 1.0f - (e2 / s);
        float lse = mx + logf(s);
        sh_nll[j * 3 + 0] = lse - l0;
        sh_nll[j * 3 + 1] = lse - l1;
        sh_nll[j * 3 + 2] = lse - l2;
    }
    for (int p = tid; p < SPAD; p += NTHREADS) { sh_row4col[p] = -1; sh_owner[p] = 0x7fffffff; }
    for (int p = tid; p < G_DIM; p += NTHREADS) sh_col4row[p] = -1;
    __syncthreads();

    const int nv = sh_nv;

    // ---- Phase 1: gather valid target params (stride 12) ----
    for (int k = tid; k < nv * 10; k += NTHREADS) {
        int i = k / 10, d = k - i * 10;
        sh_tpv[i * 12 + d] = tparams[((size_t)b * G_DIM + sh_valid[i]) * 10 + d];
    }
    __syncthreads();

    // ---- Phase 2: cost build, column-per-thread (all entries >= 0) ----
    for (int i = 0; i < nv; i++) {
        float4 t0 = *(const float4*)&sh_tpv[i * 12 + 0];
        float4 t1 = *(const float4*)&sh_tpv[i * 12 + 4];
        float  t8 = sh_tpv[i * 12 + 8];
        float  t9 = sh_tpv[i * 12 + 9];
        float acc;
        if (active) {
            acc = (sh_cls[i] == 1) ? pc1 : pc2;
            acc += 7.0f * fabsf(sp[0] - t0.x);
            acc += 7.0f * fabsf(sp[1] - t0.y);
            acc += 5.0f * fabsf(sp[2] - t0.z);
            acc += 5.0f * fabsf(sp[3] - t0.w);
            acc += 5.0f * fabsf(sp[4] - t1.x);
            acc += 5.0f * fabsf(sp[5] - t1.y);
            acc += 5.0f * fabsf(sp[6] - t1.z);
            acc += 5.0f * fabsf(sp[7] - t1.w);
            acc += 2.0f * fabsf(sp[8] - t8);
            acc += 2.0f * fabsf(sp[9] - t9);
        } else {
            acc = BIGC;
        }
        s_C[i * SPAD + j] = acc;
    }
    __syncthreads();

    // ---- Phase 3: row minima (warp per row) -> duals u + greedy candidates ----
    for (int row = wid; row < nv; row += NWARPS) {
        const float* Crow = s_C + row * SPAD;
        unsigned k_[KSLOTS]; int c_[KSLOTS];
        #pragma unroll
        for (int k = 0; k < KSLOTS; k++) {
            k_[k] = __float_as_uint(Crow[lane + 32 * k]);
            c_[k] = lane + 32 * k;
        }
        kmerge(k_[0], c_[0], k_[1], c_[1]);
        kmerge(k_[2], c_[2], k_[3], c_[3]);
        kmerge(k_[4], c_[4], k_[5], c_[5]);
        kmerge(k_[6], c_[6], k_[7], c_[7]);
        kmerge(k_[8], c_[8], k_[9], c_[9]);
        kmerge(k_[0], c_[0], k_[2], c_[2]);
        kmerge(k_[4], c_[4], k_[6], c_[6]);
        kmerge(k_[0], c_[0], k_[4], c_[4]);
        kmerge(k_[0], c_[0], k_[8], c_[8]);

        unsigned g = __reduce_min_sync(0xffffffffu, k_[0]);
        unsigned sel = (k_[0] == g) ? (unsigned)c_[0] : 0xFFFFFFFFu;
        unsigned jm = __reduce_min_sync(0xffffffffu, sel);
        if (lane == 0) { sh_u[row] = __uint_as_float(g); sh_cand[row] = (int)jm; }
    }
    __syncthreads();

    // ---- Phase 4a: parallel greedy conflict resolution (winner = min row) ----
    for (int i = tid; i < nv; i += NTHREADS)
        atomicMin_block(&sh_owner[sh_cand[i]], i);
    __syncthreads();

    if (tid < 32) {
        int base = 0;
        #pragma unroll
        for (int c = 0; c < 4; c++) {
            int i = c * 32 + tid;
            bool isfree = false;
            if (i < nv) {
                int cj = sh_cand[i];
                if (sh_owner[cj] == i) { sh_col4row[i] = cj; sh_row4col[cj] = i; }
                else isfree = true;
            }
            unsigned bal = __ballot_sync(0xffffffffu, isfree);
            if (isfree) {
                int rank = base + __popc(bal & ((1u << tid) - 1u));
                sh_free[rank] = i;
            }
            base += __popc(bal);
        }
        if (tid == 0) sh_nf = base;
    }
    __syncthreads();

    // ---- Phase 4b: warp 0 — ARR + Dijkstra (R7 version); warps 1-9 — CE base ----
    if (tid < 32) {
        float v_[KSLOTS];                  // column duals, v <= 0 always
        #pragma unroll
        for (int k = 0; k < KSLOTS; k++) v_[k] = 0.0f;

        // ---- ARR: for each free row, min1/min2 of (C - v); assign tightly ----
        int h = 0, t = sh_nf, nd = 0;
        int ops = 0;
        const int cap = 2 * nv + 8;
        while (h < t) {
            if (ops >= cap || t >= FREECAP - 1) {
                for (int q = h + (int)lane; q < t; q += 32)
                    sh_dij[nd + (q - h)] = sh_free[q];
                nd += t - h;
                break;
            }
            ops++;
            const int i = sh_free[h++];
            const float* Crow = s_C + i * SPAD;

            unsigned m1 = 0xFFFFFFFFu, m2 = 0xFFFFFFFFu; int c1 = 0;
            #pragma unroll
            for (int k = 0; k < KSLOTS; k++) {
                unsigned x = __float_as_uint(Crow[lane + 32 * k] - v_[k]);
                if (x < m1) { m2 = m1; m1 = x; c1 = lane + 32 * k; }
                else if (x < m2) m2 = x;
            }
            unsigned g1 = __reduce_min_sync(0xffffffffu, m1);
            unsigned bal = __ballot_sync(0xffffffffu, m1 == g1);
            int winlane = __ffs(bal) - 1;
            unsigned cand = (lane == winlane) ? m2 : m1;
            unsigned g2 = __reduce_min_sync(0xffffffffu, cand);
            int j1 = __shfl_sync(0xffffffffu, c1, winlane);

            int owner = sh_row4col[j1];
            if (g1 == g2 && owner >= 0) {   // exact tie on occupied col: defer
                if (lane == 0) sh_dij[nd] = i;
                nd++;
                continue;
            }
            float min1 = __uint_as_float(g1);
            float min2 = __uint_as_float(g2);
            sh_u[i] = min2;                              // lockstep same-value write
            if (g1 != g2 && lane == (j1 & 31))
                v_[j1 >> 5] -= (min2 - min1);            // tighten new arc
            sh_row4col[j1] = i;
            sh_col4row[i] = j1;
            if (owner >= 0) {
                sh_col4row[owner] = -1;
                sh_free[t++] = owner;                    // displaced row re-queued
            }
            __syncwarp();
        }
        __syncwarp();

        // ---- Dijkstra augmentation for the leftover rows ----
        for (int f = 0; f < nd; f++) {
            const int cur = sh_dij[f];
            float shortest[KSLOTS];
            unsigned scmask = 0;
            #pragma unroll
            for (int k = 0; k < KSLOTS; k++) shortest[k] = 3.0e38f;

            int   i      = cur;
            float u_i    = sh_u[cur];
            const float* Crow = s_C + i * SPAD;
            float minVal = 0.0f;
            int   tt     = 0;
            int   sink   = -1;

            while (true) {
                float base = minVal - u_i;

                unsigned k_[KSLOTS]; int c_[KSLOTS];
                #pragma unroll
                for (int k = 0; k < KSLOTS; k++) {
                    int col = lane + 32 * k;
                    c_[k] = col;
                    if (!((scmask >> k) & 1u)) {           // SC guard: load-bearing
                        float d = fmaxf(base + Crow[col] - v_[k], 0.0f);
                        if (d < shortest[k]) { shortest[k] = d; sh_path[col] = i; }
                        k_[k] = __float_as_uint(shortest[k]);
                    } else {
                        k_[k] = 0xFFFFFFFFu;
                    }
                }
                kmerge(k_[0], c_[0], k_[1], c_[1]);
                kmerge(k_[2], c_[2], k_[3], c_[3]);
                kmerge(k_[4], c_[4], k_[5], c_[5]);
                kmerge(k_[6], c_[6], k_[7], c_[7]);
                kmerge(k_[8], c_[8], k_[9], c_[9]);
                kmerge(k_[0], c_[0], k_[2], c_[2]);
                kmerge(k_[4], c_[4], k_[6], c_[6]);
                kmerge(k_[0], c_[0], k_[4], c_[4]);
                kmerge(k_[0], c_[0], k_[8], c_[8]);

                unsigned gm = __reduce_min_sync(0xffffffffu, k_[0]);
                unsigned cc = (k_[0] == gm) ? (unsigned)c_[0] : 0xFFFFFFFFu;
                unsigned js = __reduce_min_sync(0xffffffffu, cc);

                minVal = __uint_as_float(gm);
                if (lane == 0) { sh_SR[tt] = i; sh_minStep[tt] = minVal; }
                if (lane == (int)(js & 31u)) scmask |= 1u << (js >> 5);
                tt++;

                int r = sh_row4col[js];
                if (r < 0) { sink = (int)js; break; }
                i = r;
                u_i = sh_u[i];
                Crow = s_C + i * SPAD;
            }
            __syncwarp();

            if (lane == 0) sh_u[cur] += minVal;
            for (int s2 = 1 + lane; s2 < tt; s2 += 32)
                sh_u[sh_SR[s2]] += minVal - sh_minStep[s2 - 1];
            #pragma unroll
            for (int k = 0; k < KSLOTS; k++)
                if ((scmask >> k) & 1u) v_[k] -= minVal - shortest[k];
            __syncwarp();

            {
                int jj = sink;
                while (true) {
                    int i2 = sh_path[jj];
                    sh_row4col[jj] = i2;
                    int nxt = sh_col4row[i2];
                    sh_col4row[i2] = jj;
                    if (i2 == cur) break;
                    jj = nxt;
                }
            }
            __syncwarp();
        }
    } else {
        // ---- warps 1..9: CE base sum (all slots as class 0), overlapped ----
        double part = 0.0;
        for (int s = tid - 32; s < S_DIM; s += NTHREADS - 32)
            part += (double)(0.1f * sh_nll[s * 3 + 0]);
        #pragma unroll
        for (int off = 16; off; off >>= 1)
            part += __shfl_down_sync(0xffffffffu, part, off);
        if (lane == 0) sh_ceb[wid] = part;
    }
    __syncthreads();

    // ---- Phase 5: losses. CE = base + per-match correction; den closed-form ----
    double ce_corr = 0.0, csum = 0.0, wsum = 0.0;

    for (int k = tid; k < nv; k += NTHREADS) {
        int s = sh_col4row[k];
        int c = sh_cls[k];
        ce_corr += (double)sh_nll[s * 3 + c] - (double)(0.1f * sh_nll[s * 3 + 0]);
        const float* spv = sh_strokes + s * 10;
        const float* tp  = sh_tpv + k * 12;
        #pragma unroll
        for (int d8 = 0; d8 < 8; d8++) {
            float ad = fabsf(spv[d8] - tp[d8]);
            float sl = (ad < 0.1f) ? (0.5f * ad * ad / 0.1f) : (ad - 0.05f);
            csum += (double)ad + (double)sl;
        }
        wsum += (double)fabsf(spv[8] - tp[8]) + (double)fabsf(spv[9] - tp[9]);
    }

    #pragma unroll
    for (int off = 16; off; off >>= 1) {
        ce_corr += __shfl_down_sync(0xffffffffu, ce_corr, off);
        csum    += __shfl_down_sync(0xffffffffu, csum,    off);
        wsum    += __shfl_down_sync(0xffffffffu, wsum,    off);
    }
    if (lane == 0) {
        sh_acc[wid * 3 + 0] = ce_corr;
        sh_acc[wid * 3 + 1] = csum;
        sh_acc[wid * 3 + 2] = wsum;
    }
    __syncthreads();

    // ---- Phase 6: per-batch partials + fused finalize (last block) ----
    if (tid == 0) {
        double a0 = 0.0, a2 = 0.0, a3 = 0.0;
        #pragma unroll
        for (int w = 0; w < NWARPS; w++) {
            a0 += sh_acc[w * 3 + 0];
            a2 += sh_acc[w * 3 + 1];
            a3 += sh_acc[w * 3 + 2];
        }
        #pragma unroll
        for (int w = 1; w < NWARPS; w++) a0 += sh_ceb[w];
        double den = (double)(S_DIM - nv) * (double)0.1f + (double)nv;
        g_part[b * 5 + 0] = a0;
        g_part[b * 5 + 1] = den;
        g_part[b * 5 + 2] = a2;
        g_part[b * 5 + 3] = a3;
        g_part[b * 5 + 4] = (double)nv;
        __threadfence();
        unsigned old = atomicInc(&g_done, gridDim.x - 1);
        sh_last = (old == gridDim.x - 1) ? 1 : 0;
    }
    __syncthreads();

    if (sh_last && tid < 32) {
        __threadfence();
        const volatile double* gp = g_part;
        double a0 = 0.0, a1 = 0.0, a2 = 0.0, a3 = 0.0, a4 = 0.0;
        for (int bb = lane; bb < (int)gridDim.x; bb += 32) {
            a0 += gp[bb * 5 + 0];
            a1 += gp[bb * 5 + 1];
            a2 += gp[bb * 5 + 2];
            a3 += gp[bb * 5 + 3];
            a4 += gp[bb * 5 + 4];
        }
        #pragma unroll
        for (int off = 16; off; off >>= 1) {
            a0 += __shfl_down_sync(0xffffffffu, a0, off);
            a1 += __shfl_down_sync(0xffffffffu, a1, off);
            a2 += __shfl_down_sync(0xffffffffu, a2, off);
            a3 += __shfl_down_sync(0xffffffffu, a3, off);
            a4 += __shfl_down_sync(0xffffffffu, a4, off);
        }
        if (lane == 0) {
            double denom = a4 > 1.0 ? a4 : 1.0;
            double loss = CLASS_W * (a0 / a1)
                        + COORD_W * (a2 / denom)
                        + WIDTH_W * (a3 / denom);
            out[0] = (float)loss;
        }
    }
}

extern "C" void kernel_launch(void* const* d_in, const int* in_sizes, int n_in,
                              void* d_out, int out_size)
{
    const float* strokes = (const float*)d_in[0];
    const float* logits  = (const float*)d_in[1];
    const float* tparams = (const float*)d_in[2];
    const int*   tlabels = (const int*)d_in[3];

    int B = in_sizes[3] / G_DIM;
    if (B > B_MAX) B = B_MAX;

    const int dyn_smem = G_DIM * SPAD * (int)sizeof(float);   // 128000 B
    cudaFuncSetAttribute(detr_batch_kernel,
                         cudaFuncAttributeMaxDynamicSharedMemorySize, dyn_smem);

    detr_batch_kernel<<<B, NTHREADS, dyn_smem>>>(strokes, logits, tparams, tlabels,
                                                 (float*)d_out);
}

// round 10
// speedup vs baseline: 1.1406x; 1.0072x over previous
#include <cuda_runtime.h>
#include <math.h>

// Problem constants (fixed by setup_inputs: B=128, S=300, G=100)
#define S_DIM 300
#define SPAD  320
#define G_DIM 100
#define B_MAX 128
#define NTHREADS 320
#define NWARPS (NTHREADS / 32)
#define KSLOTS 10
#define BIGC  1.0e30f
#define FREECAP 256

#define CLASS_W 1.0
#define COORD_W 5.0
#define WIDTH_W 2.0
#define P0_W    2.0

static __device__ double   g_part[B_MAX * 5];
static __device__ unsigned g_done = 0;

// All costs carry a +1.0f offset so every entry is >= 0, and v only ever
// decreases (v <= 0), so C - v >= 0 and reduced Dijkstra distances >= 0.
// For non-negative IEEE floats raw bits are order-isomorphic to values, so
// argmin keys are plain __float_as_uint(x).

extern __shared__ float s_C[];    // [G_DIM * SPAD] f32 cost matrix (128 KB)

// pairwise merge preferring LEFT on ties (left = smaller column)
__device__ __forceinline__ void kmerge(unsigned& kL, int& cL, unsigned kR, int cR) {
    if (kR < kL) { kL = kR; cL = cR; }
}

// (min1,col,min2) pairwise merge; exact because b2 >= b1 always.
__device__ __forceinline__ void m12merge(unsigned& a1, int& ac, unsigned& a2,
                                         unsigned b1, int bc, unsigned b2) {
    if (b1 < a1) { a2 = (a1 < b2) ? a1 : b2; a1 = b1; ac = bc; }
    else         { a2 = (a2 < b1) ? a2 : b1; }
}

__global__ __launch_bounds__(NTHREADS, 1)
void detr_batch_kernel(const float* __restrict__ strokes,
                       const float* __restrict__ logits,
                       const float* __restrict__ tparams,
                       const int*   __restrict__ tlabels,
                       float* __restrict__ out)
{
    const int b    = blockIdx.x;
    const int tid  = threadIdx.x;
    const int wid  = tid >> 5;
    const int lane = tid & 31;

    __shared__ float  sh_strokes[S_DIM * 10];
    __shared__ float  sh_tpv[G_DIM * 12];
    __shared__ float  sh_nll[S_DIM * 3];
    __shared__ float  sh_u[G_DIM];
    __shared__ float  sh_minStep[G_DIM + 4];
    __shared__ int    sh_row4col[SPAD];
    __shared__ int    sh_col4row[G_DIM];
    __shared__ int    sh_path[SPAD];
    __shared__ int    sh_SR[G_DIM + 4];
    __shared__ int    sh_valid[G_DIM];
    __shared__ int    sh_cls[G_DIM];
    __shared__ int    sh_cand[G_DIM];
    __shared__ int    sh_free[FREECAP];
    __shared__ int    sh_dij[FREECAP];
    __shared__ int    sh_owner[SPAD];
    __shared__ int    sh_nv, sh_nf, sh_last;
    __shared__ double sh_acc[NWARPS * 3];
    __shared__ double sh_ceb[NWARPS];

    // ---- Phase 0 (warp 0): valid-target compaction; all: staging ----
    if (tid < 32) {
        int base = 0;
        #pragma unroll
        for (int c = 0; c < 4; c++) {
            int g = c * 32 + tid;
            int l = (g < G_DIM) ? tlabels[(size_t)b * G_DIM + g] : 0;
            unsigned bal = __ballot_sync(0xffffffffu, l > 0);
            if (l > 0) {
                int rank = base + __popc(bal & ((1u << tid) - 1u));
                sh_valid[rank] = g;
                sh_cls[rank]   = l;
            }
            base += __popc(bal);
        }
        if (tid == 0) sh_nv = base;
    }

    const int j = tid;
    const bool active = (j < S_DIM);

    float sp[10];
    float pc1 = 1.0f, pc2 = 1.0f;     // 1 - prob_c  (>= 0, offset folded in)
    if (active) {
        const float* g = strokes + ((size_t)b * S_DIM + j) * 10;
        #pragma unroll
        for (int d = 0; d < 10; d++) { sp[d] = g[d]; sh_strokes[j * 10 + d] = sp[d]; }

        const float* lg = logits + ((size_t)b * S_DIM + j) * 3;
        float l0 = lg[0], l1 = lg[1], l2 = lg[2];
        float mx = fmaxf(l0, fmaxf(l1, l2));
        float e0 = expf(l0 - mx), e1 = expf(l1 - mx), e2 = expf(l2 - mx);
        float s  = e0 + e1 + e2;
        pc1 = 1.0f - (e1 / s);
        pc2 = 1.0f - (e2 / s);
        float lse = mx + logf(s);
        sh_nll[j * 3 + 0] = lse - l0;
        sh_nll[j * 3 + 1] = lse - l1;
        sh_nll[j * 3 + 2] = lse - l2;
    }
    for (int p = tid; p < SPAD; p += NTHREADS) { sh_row4col[p] = -1; sh_owner[p] = 0x7fffffff; }
    for (int p = tid; p < G_DIM; p += NTHREADS) sh_col4row[p] = -1;
    __syncthreads();

    const int nv = sh_nv;

    // ---- Phase 1: gather valid target params (stride 12) ----
    for (int k = tid; k < nv * 10; k += NTHREADS) {
        int i = k / 10, d = k - i * 10;
        sh_tpv[i * 12 + d] = tparams[((size_t)b * G_DIM + sh_valid[i]) * 10 + d];
    }
    __syncthreads();

    // ---- Phase 2: cost build, column-per-thread (all entries >= 0) ----
    for (int i = 0; i < nv; i++) {
        float4 t0 = *(const float4*)&sh_tpv[i * 12 + 0];
        float4 t1 = *(const float4*)&sh_tpv[i * 12 + 4];
        float  t8 = sh_tpv[i * 12 + 8];
        float  t9 = sh_tpv[i * 12 + 9];
        float acc;
        if (active) {
            acc = (sh_cls[i] == 1) ? pc1 : pc2;
            acc += 7.0f * fabsf(sp[0] - t0.x);
            acc += 7.0f * fabsf(sp[1] - t0.y);
            acc += 5.0f * fabsf(sp[2] - t0.z);
            acc += 5.0f * fabsf(sp[3] - t0.w);
            acc += 5.0f * fabsf(sp[4] - t1.x);
            acc += 5.0f * fabsf(sp[5] - t1.y);
            acc += 5.0f * fabsf(sp[6] - t1.z);
            acc += 5.0f * fabsf(sp[7] - t1.w);
            acc += 2.0f * fabsf(sp[8] - t8);
            acc += 2.0f * fabsf(sp[9] - t9);
        } else {
            acc = BIGC;
        }
        s_C[i * SPAD + j] = acc;
    }
    __syncthreads();

    // ---- Phase 3: row minima (warp per row) -> duals u + greedy candidates ----
    for (int row = wid; row < nv; row += NWARPS) {
        const float* Crow = s_C + row * SPAD;
        unsigned k_[KSLOTS]; int c_[KSLOTS];
        #pragma unroll
        for (int k = 0; k < KSLOTS; k++) {
            k_[k] = __float_as_uint(Crow[lane + 32 * k]);
            c_[k] = lane + 32 * k;
        }
        kmerge(k_[0], c_[0], k_[1], c_[1]);
        kmerge(k_[2], c_[2], k_[3], c_[3]);
        kmerge(k_[4], c_[4], k_[5], c_[5]);
        kmerge(k_[6], c_[6], k_[7], c_[7]);
        kmerge(k_[8], c_[8], k_[9], c_[9]);
        kmerge(k_[0], c_[0], k_[2], c_[2]);
        kmerge(k_[4], c_[4], k_[6], c_[6]);
        kmerge(k_[0], c_[0], k_[4], c_[4]);
        kmerge(k_[0], c_[0], k_[8], c_[8]);

        unsigned g = __reduce_min_sync(0xffffffffu, k_[0]);
        unsigned sel = (k_[0] == g) ? (unsigned)c_[0] : 0xFFFFFFFFu;
        unsigned jm = __reduce_min_sync(0xffffffffu, sel);
        if (lane == 0) { sh_u[row] = __uint_as_float(g); sh_cand[row] = (int)jm; }
    }
    __syncthreads();

    // ---- Phase 4a: parallel greedy conflict resolution (winner = min row) ----
    for (int i = tid; i < nv; i += NTHREADS)
        atomicMin_block(&sh_owner[sh_cand[i]], i);
    __syncthreads();

    if (tid < 32) {
        int base = 0;
        #pragma unroll
        for (int c = 0; c < 4; c++) {
            int i = c * 32 + tid;
            bool isfree = false;
            if (i < nv) {
                int cj = sh_cand[i];
                if (sh_owner[cj] == i) { sh_col4row[i] = cj; sh_row4col[cj] = i; }
                else isfree = true;
            }
            unsigned bal = __ballot_sync(0xffffffffu, isfree);
            if (isfree) {
                int rank = base + __popc(bal & ((1u << tid) - 1u));
                sh_free[rank] = i;
            }
            base += __popc(bal);
        }
        if (tid == 0) sh_nf = base;
    }
    __syncthreads();

    // ---- Phase 4b: warp 0 — ARR + Dijkstra; warps 1-9 — CE base (overlap) ----
    if (tid < 32) {
        float v_[KSLOTS];                  // column duals, v <= 0 always
        #pragma unroll
        for (int k = 0; k < KSLOTS; k++) v_[k] = 0.0f;

        // ---- ARR: tree min1/min2; free-column fast path; no per-iter sync ----
        int h = 0, t = sh_nf, nd = 0;
        int ops = 0;
        const int cap = 2 * nv + 8;
        while (h < t) {
            if (ops >= cap || t >= FREECAP - 1) {
                for (int q = h + (int)lane; q < t; q += 32)
                    sh_dij[nd + (q - h)] = sh_free[q];
                nd += t - h;
                break;
            }
            ops++;
            const int i = sh_free[h++];
            const float* Crow = s_C + i * SPAD;

            // leaf pairs: slots (2k, 2k+1); independent loads, depth-4 merge tree
            unsigned a1[5], a2[5]; int ac[5];
            #pragma unroll
            for (int k = 0; k < 5; k++) {
                int colL = lane + 64 * k;
                int colR = colL + 32;
                unsigned xL = __float_as_uint(Crow[colL] - v_[2 * k]);
                unsigned xR = __float_as_uint(Crow[colR] - v_[2 * k + 1]);
                if (xR < xL) { a1[k] = xR; ac[k] = colR; a2[k] = xL; }
                else         { a1[k] = xL; ac[k] = colL; a2[k] = xR; }
            }
            m12merge(a1[0], ac[0], a2[0], a1[1], ac[1], a2[1]);
            m12merge(a1[2], ac[2], a2[2], a1[3], ac[3], a2[3]);
            m12merge(a1[0], ac[0], a2[0], a1[2], ac[2], a2[2]);
            m12merge(a1[0], ac[0], a2[0], a1[4], ac[4], a2[4]);

            unsigned g1 = __reduce_min_sync(0xffffffffu, a1[0]);
            unsigned bal = __ballot_sync(0xffffffffu, a1[0] == g1);
            int winlane = __ffs(bal) - 1;
            int j1 = __shfl_sync(0xffffffffu, ac[0], winlane);

            int owner = sh_row4col[j1];
            if (owner < 0) {
                // free column: tight assignment at min1; v untouched, no min2
                sh_u[i] = __uint_as_float(g1);
                sh_row4col[j1] = i;
                sh_col4row[i] = j1;
                continue;
            }

            unsigned cand = (lane == winlane) ? a2[0] : a1[0];
            unsigned g2 = __reduce_min_sync(0xffffffffu, cand);
            if (g1 == g2) {                 // exact tie on occupied col: defer
                if (lane == 0) sh_dij[nd] = i;
                nd++;
                continue;
            }
            float min1 = __uint_as_float(g1);
            float min2 = __uint_as_float(g2);
            sh_u[i] = min2;                              // lockstep same-value write
            if (lane == (j1 & 31))
                v_[j1 >> 5] -= (min2 - min1);            // tighten new arc
            sh_row4col[j1] = i;
            sh_col4row[i] = j1;
            sh_col4row[owner] = -1;
            sh_free[t++] = owner;                        // displaced row re-queued
        }
        __syncwarp();

        // ---- Dijkstra augmentation for the leftover rows ----
        for (int f = 0; f < nd; f++) {
            const int cur = sh_dij[f];
            float shortest[KSLOTS];
            unsigned scmask = 0;
            #pragma unroll
            for (int k = 0; k < KSLOTS; k++) shortest[k] = 3.0e38f;

            int   i      = cur;
            float u_i    = sh_u[cur];
            const float* Crow = s_C + i * SPAD;
            float minVal = 0.0f;
            int   tt     = 0;
            int   sink   = -1;

            while (true) {
                float base = minVal - u_i;

                unsigned k_[KSLOTS]; int c_[KSLOTS];
                #pragma unroll
                for (int k = 0; k < KSLOTS; k++) {
                    int col = lane + 32 * k;
                    c_[k] = col;
                    if (!((scmask >> k) & 1u)) {           // SC guard: load-bearing
                        float d = fmaxf(base + Crow[col] - v_[k], 0.0f);
                        if (d < shortest[k]) { shortest[k] = d; sh_path[col] = i; }
                        k_[k] = __float_as_uint(shortest[k]);
                    } else {
                        k_[k] = 0xFFFFFFFFu;
                    }
                }
                kmerge(k_[0], c_[0], k_[1], c_[1]);
                kmerge(k_[2], c_[2], k_[3], c_[3]);
                kmerge(k_[4], c_[4], k_[5], c_[5]);
                kmerge(k_[6], c_[6], k_[7], c_[7]);
                kmerge(k_[8], c_[8], k_[9], c_[9]);
                kmerge(k_[0], c_[0], k_[2], c_[2]);
                kmerge(k_[4], c_[4], k_[6], c_[6]);
                kmerge(k_[0], c_[0], k_[4], c_[4]);
                kmerge(k_[0], c_[0], k_[8], c_[8]);

                unsigned gm = __reduce_min_sync(0xffffffffu, k_[0]);
                unsigned cc = (k_[0] == gm) ? (unsigned)c_[0] : 0xFFFFFFFFu;
                unsigned js = __reduce_min_sync(0xffffffffu, cc);

                minVal = __uint_as_float(gm);
                if (lane == 0) { sh_SR[tt] = i; sh_minStep[tt] = minVal; }
                if (lane == (int)(js & 31u)) scmask |= 1u << (js >> 5);
                tt++;

                int r = sh_row4col[js];
                if (r < 0) { sink = (int)js; break; }
                i = r;
                u_i = sh_u[i];
                Crow = s_C + i * SPAD;
            }
            __syncwarp();

            if (lane == 0) sh_u[cur] += minVal;
            for (int s2 = 1 + lane; s2 < tt; s2 += 32)
                sh_u[sh_SR[s2]] += minVal - sh_minStep[s2 - 1];
            #pragma unroll
            for (int k = 0; k < KSLOTS; k++)
                if ((scmask >> k) & 1u) v_[k] -= minVal - shortest[k];
            __syncwarp();

            {
                int jj = sink;
                while (true) {
                    int i2 = sh_path[jj];
                    sh_row4col[jj] = i2;
                    int nxt = sh_col4row[i2];
                    sh_col4row[i2] = jj;
                    if (i2 == cur) break;
                    jj = nxt;
                }
            }
            __syncwarp();
        }
    } else {
        // ---- warps 1..9: CE base sum (all slots as class 0), overlapped ----
        double part = 0.0;
        for (int s = tid - 32; s < S_DIM; s += NTHREADS - 32)
            part += (double)(0.1f * sh_nll[s * 3 + 0]);
        #pragma unroll
        for (int off = 16; off; off >>= 1)
            part += __shfl_down_sync(0xffffffffu, part, off);
        if (lane == 0) sh_ceb[wid] = part;
    }
    __syncthreads();

    // ---- Phase 5: losses. CE = base + per-match correction; den closed-form ----
    double ce_corr = 0.0, csum = 0.0, wsum = 0.0;

    for (int k = tid; k < nv; k += NTHREADS) {
        int s = sh_col4row[k];
        int c = sh_cls[k];
        ce_corr += (double)sh_nll[s * 3 + c] - (double)(0.1f * sh_nll[s * 3 + 0]);
        const float* spv = sh_strokes + s * 10;
        const float* tp  = sh_tpv + k * 12;
        #pragma unroll
        for (int d8 = 0; d8 < 8; d8++) {
            float ad = fabsf(spv[d8] - tp[d8]);
            float sl = (ad < 0.1f) ? (0.5f * ad * ad / 0.1f) : (ad - 0.05f);
            csum += (double)ad + (double)sl;
        }
        wsum += (double)fabsf(spv[8] - tp[8]) + (double)fabsf(spv[9] - tp[9]);
    }

    #pragma unroll
    for (int off = 16; off; off >>= 1) {
        ce_corr += __shfl_down_sync(0xffffffffu, ce_corr, off);
        csum    += __shfl_down_sync(0xffffffffu, csum,    off);
        wsum    += __shfl_down_sync(0xffffffffu, wsum,    off);
    }
    if (lane == 0) {
        sh_acc[wid * 3 + 0] = ce_corr;
        sh_acc[wid * 3 + 1] = csum;
        sh_acc[wid * 3 + 2] = wsum;
    }
    __syncthreads();

    // ---- Phase 6: per-batch partials + fused finalize (last block) ----
    if (tid == 0) {
        double a0 = 0.0, a2 = 0.0, a3 = 0.0;
        #pragma unroll
        for (int w = 0; w < NWARPS; w++) {
            a0 += sh_acc[w * 3 + 0];
            a2 += sh_acc[w * 3 + 1];
            a3 += sh_acc[w * 3 + 2];
        }
        #pragma unroll
        for (int w = 1; w < NWARPS; w++) a0 += sh_ceb[w];
        double den = (double)(S_DIM - nv) * (double)0.1f + (double)nv;
        g_part[b * 5 + 0] = a0;
        g_part[b * 5 + 1] = den;
        g_part[b * 5 + 2] = a2;
        g_part[b * 5 + 3] = a3;
        g_part[b * 5 + 4] = (double)nv;
        __threadfence();
        unsigned old = atomicInc(&g_done, gridDim.x - 1);
        sh_last = (old == gridDim.x - 1) ? 1 : 0;
    }
    __syncthreads();

    if (sh_last && tid < 32) {
        __threadfence();
        const volatile double* gp = g_part;
        double a0 = 0.0, a1 = 0.0, a2 = 0.0, a3 = 0.0, a4 = 0.0;
        for (int bb = lane; bb < (int)gridDim.x; bb += 32) {
            a0 += gp[bb * 5 + 0];
            a1 += gp[bb * 5 + 1];
            a2 += gp[bb * 5 + 2];
            a3 += gp[bb * 5 + 3];
            a4 += gp[bb * 5 + 4];
        }
        #pragma unroll
        for (int off = 16; off; off >>= 1) {
            a0 += __shfl_down_sync(0xffffffffu, a0, off);
            a1 += __shfl_down_sync(0xffffffffu, a1, off);
            a2 += __shfl_down_sync(0xffffffffu, a2, off);
            a3 += __shfl_down_sync(0xffffffffu, a3, off);
            a4 += __shfl_down_sync(0xffffffffu, a4, off);
        }
        if (lane == 0) {
            double denom = a4 > 1.0 ? a4 : 1.0;
            double loss = CLASS_W * (a0 / a1)
                        + COORD_W * (a2 / denom)
                        + WIDTH_W * (a3 / denom);
            out[0] = (float)loss;
        }
    }
}

extern "C" void kernel_launch(void* const* d_in, const int* in_sizes, int n_in,
                              void* d_out, int out_size)
{
    const float* strokes = (const float*)d_in[0];
    const float* logits  = (const float*)d_in[1];
    const float* tparams = (const float*)d_in[2];
    const int*   tlabels = (const int*)d_in[3];

    int B = in_sizes[3] / G_DIM;
    if (B > B_MAX) B = B_MAX;

    const int dyn_smem = G_DIM * SPAD * (int)sizeof(float);   // 128000 B
    cudaFuncSetAttribute(detr_batch_kernel,
                         cudaFuncAttributeMaxDynamicSharedMemorySize, dyn_smem);

    detr_batch_kernel<<<B, NTHREADS, dyn_smem>>>(strokes, logits, tparams, tlabels,
                                                 (float*)d_out);
}